// round 1
// baseline (speedup 1.0000x reference)
#include <cuda_runtime.h>
#include <math.h>

// ---------------- problem constants ----------------
#define BATCH   8192
#define D0      1024
#define D1      768
#define DIB     1024
#define KCAT    2816        // D0 + D1 + DIB
#define DOUT    1536
#define H1C     512
#define H2C     100
#define NEXP    7

// ---------------- device scratch (no allocations allowed) ----------------
__device__ float g_Wavg [KCAT * DOUT];       // stacked averaged weights  [2816,1536]
__device__ float g_bavg [3 * DOUT];          // averaged biases per source
__device__ float g_Xcat [BATCH * KCAT];      // w-scaled concatenated inputs
__device__ float g_h1   [BATCH * H1C];
__device__ float g_h2   [BATCH * H2C];
__device__ float g_stats1[2 * H1C];          // [sum, sumsq] per column
__device__ float g_stats2[2 * H2C];
__device__ float g_w    [BATCH * 3];

// ---------------- utility kernels ----------------
__global__ void zero_stats_kernel() {
    int i = blockIdx.x * blockDim.x + threadIdx.x;
    if (i < 2 * H1C) g_stats1[i] = 0.0f;
    if (i < 2 * H2C) g_stats2[i] = 0.0f;
}

// Average the 7 expert weight matrices per source into stacked g_Wavg.
__global__ void avg_weights_kernel(const float* __restrict__ pW0,
                                   const float* __restrict__ pW1,
                                   const float* __restrict__ pWib) {
    const int C4 = DOUT / 4;                 // 384 float4 per row
    const int total = KCAT * C4;
    for (int idx = blockIdx.x * blockDim.x + threadIdx.x; idx < total;
         idx += gridDim.x * blockDim.x) {
        int row = idx / C4;
        int c   = (idx - row * C4) * 4;
        const float* src; int lrow; int ld;
        if (row < D0)            { src = pW0;  lrow = row;            ld = D0;  }
        else if (row < D0 + D1)  { src = pW1;  lrow = row - D0;       ld = D1;  }
        else                     { src = pWib; lrow = row - D0 - D1;  ld = DIB; }
        const float* base = src + (size_t)lrow * DOUT + c;
        const size_t estride = (size_t)ld * DOUT;
        float4 acc = make_float4(0.f, 0.f, 0.f, 0.f);
        #pragma unroll
        for (int e = 0; e < NEXP; e++) {
            float4 v = *reinterpret_cast<const float4*>(base + (size_t)e * estride);
            acc.x += v.x; acc.y += v.y; acc.z += v.z; acc.w += v.w;
        }
        const float inv7 = 1.0f / 7.0f;
        acc.x *= inv7; acc.y *= inv7; acc.z *= inv7; acc.w *= inv7;
        *reinterpret_cast<float4*>(&g_Wavg[(size_t)row * DOUT + c]) = acc;
    }
}

__global__ void avg_bias_kernel(const float* __restrict__ pb0,
                                const float* __restrict__ pb1,
                                const float* __restrict__ pbib) {
    int i = blockIdx.x * blockDim.x + threadIdx.x;
    if (i >= 3 * DOUT) return;
    int s = i / DOUT, n = i - s * DOUT;
    const float* pb = (s == 0) ? pb0 : (s == 1) ? pb1 : pbib;
    float a = 0.f;
    #pragma unroll
    for (int e = 0; e < NEXP; e++) a += pb[e * DOUT + n];
    g_bavg[i] = a * (1.0f / 7.0f);
}

// ---------------- SGEMM: C[M,N] = A[M,K] @ B[K,N] (+bias) ----------------
// 128x128 block, BK=8, 8x8 microtile split as 4+4 vector fragments.
template<bool NGUARD>
__global__ void __launch_bounds__(256, 2)
sgemm_kernel(const float* __restrict__ A, const float* __restrict__ Bm,
             const float* __restrict__ bias, float* __restrict__ C,
             int M, int N, int K) {
    __shared__ float As[8][128];
    __shared__ float Bs[8][128];
    const int bm = blockIdx.y * 128;
    const int bn = blockIdx.x * 128;
    const int tid  = threadIdx.x;
    const int arow = tid >> 1;            // 0..127
    const int acol = (tid & 1) << 2;      // 0 or 4
    const int brow = tid >> 5;            // 0..7
    const int bcol = (tid & 31) << 2;     // 0..124
    const int tx = tid & 15;
    const int ty = tid >> 4;

    float acc[8][8];
    #pragma unroll
    for (int i = 0; i < 8; i++)
        #pragma unroll
        for (int j = 0; j < 8; j++) acc[i][j] = 0.f;

    for (int k0 = 0; k0 < K; k0 += 8) {
        float4 av = *reinterpret_cast<const float4*>(
            A + (size_t)(bm + arow) * K + k0 + acol);
        As[acol + 0][arow] = av.x;
        As[acol + 1][arow] = av.y;
        As[acol + 2][arow] = av.z;
        As[acol + 3][arow] = av.w;
        if (!NGUARD) {
            float4 bv = *reinterpret_cast<const float4*>(
                Bm + (size_t)(k0 + brow) * N + bn + bcol);
            *reinterpret_cast<float4*>(&Bs[brow][bcol]) = bv;
        } else {
            #pragma unroll
            for (int j = 0; j < 4; j++) {
                int n = bn + bcol + j;
                Bs[brow][bcol + j] = (n < N) ? Bm[(size_t)(k0 + brow) * N + n] : 0.f;
            }
        }
        __syncthreads();
        #pragma unroll
        for (int kk = 0; kk < 8; kk++) {
            float4 a0 = *reinterpret_cast<const float4*>(&As[kk][ty * 4]);
            float4 a1 = *reinterpret_cast<const float4*>(&As[kk][64 + ty * 4]);
            float4 b0 = *reinterpret_cast<const float4*>(&Bs[kk][tx * 4]);
            float4 b1 = *reinterpret_cast<const float4*>(&Bs[kk][64 + tx * 4]);
            float a[8] = {a0.x, a0.y, a0.z, a0.w, a1.x, a1.y, a1.z, a1.w};
            float b[8] = {b0.x, b0.y, b0.z, b0.w, b1.x, b1.y, b1.z, b1.w};
            #pragma unroll
            for (int i = 0; i < 8; i++)
                #pragma unroll
                for (int j = 0; j < 8; j++)
                    acc[i][j] = fmaf(a[i], b[j], acc[i][j]);
        }
        __syncthreads();
    }

    #pragma unroll
    for (int i = 0; i < 8; i++) {
        int m = bm + ((i < 4) ? (ty * 4 + i) : (64 + ty * 4 + (i - 4)));
        #pragma unroll
        for (int j = 0; j < 8; j++) {
            int n = bn + ((j < 4) ? (tx * 4 + j) : (64 + tx * 4 + (j - 4)));
            if (!NGUARD || n < N) {
                float v = acc[i][j];
                if (bias) v += bias[n];
                C[(size_t)m * N + n] = v;
            }
        }
    }
}

// ---------------- per-column sum / sumsq (for BN batch stats) ----------------
__global__ void col_stats_kernel(const float* __restrict__ H,
                                 float* __restrict__ stats, int Brows, int C) {
    int c = blockIdx.x * 32 + threadIdx.x;
    int chunk = (Brows + gridDim.y - 1) / gridDim.y;
    int r0 = blockIdx.y * chunk;
    int r1 = min(Brows, r0 + chunk);
    float s = 0.f, s2 = 0.f;
    if (c < C) {
        for (int r = r0 + threadIdx.y; r < r1; r += 8) {
            float v = H[(size_t)r * C + c];
            s += v;
            s2 = fmaf(v, v, s2);
        }
    }
    __shared__ float sh[8][2][32];
    sh[threadIdx.y][0][threadIdx.x] = s;
    sh[threadIdx.y][1][threadIdx.x] = s2;
    __syncthreads();
    if (threadIdx.y == 0 && c < C) {
        float ts = 0.f, ts2 = 0.f;
        #pragma unroll
        for (int y = 0; y < 8; y++) { ts += sh[y][0][threadIdx.x]; ts2 += sh[y][1][threadIdx.x]; }
        atomicAdd(&stats[c], ts);
        atomicAdd(&stats[C + c], ts2);
    }
}

// ---------------- BN + ReLU in place on g_h1 ----------------
__global__ void bn_relu_h1_kernel(const float* __restrict__ gamma,
                                  const float* __restrict__ beta) {
    const int total = BATCH * H1C;
    const float invB = 1.0f / (float)BATCH;
    for (int i = blockIdx.x * blockDim.x + threadIdx.x; i < total;
         i += gridDim.x * blockDim.x) {
        int c = i & (H1C - 1);                  // H1C = 512, power of two
        float mean = g_stats1[c] * invB;
        float var  = g_stats1[H1C + c] * invB - mean * mean;
        float inv  = rsqrtf(var + 1e-5f);
        float v = g_h1[i];
        v = gamma[c] * (v - mean) * inv + beta[c];
        g_h1[i] = fmaxf(v, 0.f);
    }
}

// ---------------- fused BN+tanh + Linear(100,3) + sigmoid + softmax ----------------
__global__ void router_final_kernel(const float* __restrict__ rg2,
                                    const float* __restrict__ rbt2,
                                    const float* __restrict__ rw3,
                                    const float* __restrict__ rb3) {
    int warp = (blockIdx.x * blockDim.x + threadIdx.x) >> 5;
    int lane = threadIdx.x & 31;
    if (warp >= BATCH) return;
    const float invB = 1.0f / (float)BATCH;
    float d0 = 0.f, d1 = 0.f, d2 = 0.f;
    for (int c = lane; c < H2C; c += 32) {
        float mean = g_stats2[c] * invB;
        float var  = g_stats2[H2C + c] * invB - mean * mean;
        float v = g_h2[(size_t)warp * H2C + c];
        v = rg2[c] * (v - mean) * rsqrtf(var + 1e-5f) + rbt2[c];
        v = tanhf(v);
        d0 = fmaf(v, rw3[c * 3 + 0], d0);
        d1 = fmaf(v, rw3[c * 3 + 1], d1);
        d2 = fmaf(v, rw3[c * 3 + 2], d2);
    }
    #pragma unroll
    for (int o = 16; o > 0; o >>= 1) {
        d0 += __shfl_down_sync(0xffffffffu, d0, o);
        d1 += __shfl_down_sync(0xffffffffu, d1, o);
        d2 += __shfl_down_sync(0xffffffffu, d2, o);
    }
    if (lane == 0) {
        float l0 = 1.f / (1.f + __expf(-(d0 + rb3[0])));
        float l1 = 1.f / (1.f + __expf(-(d1 + rb3[1])));
        float l2 = 1.f / (1.f + __expf(-(d2 + rb3[2])));
        float mx = fmaxf(l0, fmaxf(l1, l2));
        float e0 = __expf(l0 - mx), e1 = __expf(l1 - mx), e2 = __expf(l2 - mx);
        float inv = 1.f / (e0 + e1 + e2);
        g_w[warp * 3 + 0] = e0 * inv;
        g_w[warp * 3 + 1] = e1 * inv;
        g_w[warp * 3 + 2] = e2 * inv;
    }
}

// ---------------- Xcat[b,:] = [w0*x0[b] | w1*x1[b] | w2*xib[b]] ----------------
__global__ void scale_concat_kernel(const float* __restrict__ x0,
                                    const float* __restrict__ x1,
                                    const float* __restrict__ xib) {
    const int K4 = KCAT / 4;                  // 704
    const int total = BATCH * K4;
    for (int idx = blockIdx.x * blockDim.x + threadIdx.x; idx < total;
         idx += gridDim.x * blockDim.x) {
        int b = idx / K4;
        int c = (idx - b * K4) * 4;
        float w; float4 v;
        if (c < D0) {
            w = g_w[b * 3 + 0];
            v = *reinterpret_cast<const float4*>(x0 + (size_t)b * D0 + c);
        } else if (c < D0 + D1) {
            w = g_w[b * 3 + 1];
            v = *reinterpret_cast<const float4*>(x1 + (size_t)b * D1 + (c - D0));
        } else {
            w = g_w[b * 3 + 2];
            v = *reinterpret_cast<const float4*>(xib + (size_t)b * DIB + (c - D0 - D1));
        }
        v.x *= w; v.y *= w; v.z *= w; v.w *= w;
        *reinterpret_cast<float4*>(&g_Xcat[(size_t)b * KCAT + c]) = v;
    }
}

// ---------------- add w·b̄ bias + L2-normalize each output row ----------------
__global__ void normalize_rows_kernel(float* __restrict__ out) {
    int b = blockIdx.x;
    int t = threadIdx.x;                      // 256 threads, 6 cols each
    float w0 = g_w[b * 3 + 0], w1 = g_w[b * 3 + 1], w2 = g_w[b * 3 + 2];
    float vals[6];
    float ss = 0.f;
    #pragma unroll
    for (int j = 0; j < 6; j++) {
        int n = t + j * 256;
        float v = out[(size_t)b * DOUT + n];
        v += w0 * g_bavg[n] + w1 * g_bavg[DOUT + n] + w2 * g_bavg[2 * DOUT + n];
        vals[j] = v;
        ss = fmaf(v, v, ss);
    }
    __shared__ float red[256];
    red[t] = ss;
    __syncthreads();
    #pragma unroll
    for (int s2 = 128; s2 > 0; s2 >>= 1) {
        if (t < s2) red[t] += red[t + s2];
        __syncthreads();
    }
    float inv = 1.f / fmaxf(sqrtf(red[0]), 1e-12f);
    #pragma unroll
    for (int j = 0; j < 6; j++)
        out[(size_t)b * DOUT + t + j * 256] = vals[j] * inv;
}

// ---------------- launch ----------------
extern "C" void kernel_launch(void* const* d_in, const int* in_sizes, int n_in,
                              void* d_out, int out_size) {
    const float* x0   = (const float*)d_in[0];
    const float* x1   = (const float*)d_in[1];
    const float* xib  = (const float*)d_in[2];
    const float* pW0  = (const float*)d_in[3];
    const float* pb0  = (const float*)d_in[4];
    const float* pW1  = (const float*)d_in[5];
    const float* pb1  = (const float*)d_in[6];
    const float* pWib = (const float*)d_in[7];
    const float* pbib = (const float*)d_in[8];
    const float* rw1  = (const float*)d_in[9];
    const float* rb1  = (const float*)d_in[10];
    const float* rg1  = (const float*)d_in[11];
    const float* rbt1 = (const float*)d_in[12];
    const float* rw2  = (const float*)d_in[13];
    const float* rb2  = (const float*)d_in[14];
    const float* rg2  = (const float*)d_in[15];
    const float* rbt2 = (const float*)d_in[16];
    const float* rw3  = (const float*)d_in[17];
    const float* rb3  = (const float*)d_in[18];
    float* out = (float*)d_out;
    (void)in_sizes; (void)n_in; (void)out_size;

    // resolve scratch addresses (no allocation; just symbol lookup)
    void *wavg_p, *xcat_p, *h1_p, *h2_p, *s1_p, *s2_p;
    cudaGetSymbolAddress(&wavg_p, g_Wavg);
    cudaGetSymbolAddress(&xcat_p, g_Xcat);
    cudaGetSymbolAddress(&h1_p, g_h1);
    cudaGetSymbolAddress(&h2_p, g_h2);
    cudaGetSymbolAddress(&s1_p, g_stats1);
    cudaGetSymbolAddress(&s2_p, g_stats2);
    float* Wavg = (float*)wavg_p;
    float* Xcat = (float*)xcat_p;
    float* h1   = (float*)h1_p;
    float* h2   = (float*)h2_p;
    float* st1  = (float*)s1_p;
    float* st2  = (float*)s2_p;

    zero_stats_kernel<<<4, 256>>>();
    avg_weights_kernel<<<2048, 256>>>(pW0, pW1, pWib);
    avg_bias_kernel<<<(3 * DOUT + 255) / 256, 256>>>(pb0, pb1, pbib);

    // router layer 1: h1 = x0 @ rw1 + rb1   (M=8192, N=512, K=1024)
    sgemm_kernel<false><<<dim3(H1C / 128, BATCH / 128), 256>>>(
        x0, rw1, rb1, h1, BATCH, H1C, D0);
    col_stats_kernel<<<dim3(H1C / 32, 16), dim3(32, 8)>>>(h1, st1, BATCH, H1C);
    bn_relu_h1_kernel<<<4096, 256>>>(rg1, rbt1);

    // router layer 2: h2 = h1 @ rw2 + rb2   (M=8192, N=100, K=512)
    sgemm_kernel<true><<<dim3(1, BATCH / 128), 256>>>(
        h1, rw2, rb2, h2, BATCH, H2C, H1C);
    col_stats_kernel<<<dim3((H2C + 31) / 32, 16), dim3(32, 8)>>>(h2, st2, BATCH, H2C);
    router_final_kernel<<<BATCH * 32 / 256, 256>>>(rg2, rbt2, rw3, rb3);

    // weighted concat + fused big GEMM: out = Xcat @ Wavg
    scale_concat_kernel<<<8192, 256>>>(x0, x1, xib);
    sgemm_kernel<false><<<dim3(DOUT / 128, BATCH / 128), 256>>>(
        Xcat, Wavg, nullptr, out, BATCH, DOUT, KCAT);

    normalize_rows_kernel<<<BATCH, 256>>>(out);
}

// round 3
// speedup vs baseline: 2.3746x; 2.3746x over previous
#include <cuda_runtime.h>
#include <cuda_bf16.h>
#include <cstdint>
#include <math.h>

// ---------------- problem constants ----------------
#define BATCH   8192
#define D0      1024
#define D1      768
#define DIB     1024
#define KCAT    2816        // D0 + D1 + DIB
#define DOUT    1536
#define H1C     512
#define H2C     100
#define NEXP    7

#define KP_BIG  (3*KCAT)    // 8448  (split-bf16: [ah|ah|al] x [bh|bl|bh])
#define KP_R1   (3*D0)      // 3072

// ---------------- device scratch (no allocations allowed) ----------------
__device__ __nv_bfloat16 g_A [(size_t)BATCH * KP_BIG];   // 138 MB
__device__ __nv_bfloat16 g_B [(size_t)DOUT  * KP_BIG];   // 26 MB   [n][k'] K-major rows
__device__ __nv_bfloat16 g_A1[(size_t)BATCH * KP_R1];    // 50 MB
__device__ __nv_bfloat16 g_B1[(size_t)H1C   * KP_R1];    // 3 MB
__device__ float g_h1   [BATCH * H1C];
__device__ float g_h2   [BATCH * H2C];
__device__ float g_stats1[2 * H1C];
__device__ float g_stats2[2 * H2C];
__device__ float g_w    [BATCH * 3];
__device__ float g_bavg [3 * DOUT];

// ---------------- PTX helpers (base-target safe: sm_80+ ISA only) ------------
__device__ __forceinline__ uint32_t smem_u32(const void* p) {
    uint32_t a;
    asm("{ .reg .u64 t; cvta.to.shared.u64 t, %1; cvt.u32.u64 %0, t; }"
        : "=r"(a) : "l"(p));
    return a;
}
__device__ __forceinline__ void cp16(uint32_t saddr, const void* g) {
    asm volatile("cp.async.cg.shared.global [%0], [%1], 16;"
                 :: "r"(saddr), "l"(g));
}
__device__ __forceinline__ void ldsm4(uint32_t* r, uint32_t addr) {
    asm volatile("ldmatrix.sync.aligned.m8n8.x4.shared.b16 {%0,%1,%2,%3}, [%4];"
                 : "=r"(r[0]), "=r"(r[1]), "=r"(r[2]), "=r"(r[3]) : "r"(addr));
}
__device__ __forceinline__ void mma_bf16(float* c, const uint32_t* a,
                                         uint32_t b0, uint32_t b1) {
    asm volatile(
        "mma.sync.aligned.m16n8k16.row.col.f32.bf16.bf16.f32 "
        "{%0,%1,%2,%3}, {%4,%5,%6,%7}, {%8,%9}, {%0,%1,%2,%3};"
        : "+f"(c[0]), "+f"(c[1]), "+f"(c[2]), "+f"(c[3])
        : "r"(a[0]), "r"(a[1]), "r"(a[2]), "r"(a[3]), "r"(b0), "r"(b1));
}

// ---------------- HMMA bf16 GEMM: C[M,N] = A[M,Kp] @ B[N,Kp]^T ----------------
// CTA 128x128, BK=64 bf16 (128B rows, SW128 swizzle), 3-stage cp.async pipeline.
// 8 warps in 2(m) x 4(n); warp tile 64x32; mma.sync.m16n8k16.
#define STAGE_BYTES 32768               // A 16KB + B 16KB
#define HM_SMEM     (3 * STAGE_BYTES)   // 98304

__global__ void __launch_bounds__(256, 2)
hmma_gemm_kernel(const __nv_bfloat16* __restrict__ A,
                 const __nv_bfloat16* __restrict__ B,
                 float* __restrict__ C,
                 int ldA, int ldB, int ldC, int nchunks) {
    extern __shared__ char smem[];
    const uint32_t sbase = smem_u32(smem);
    const int tid  = threadIdx.x;
    const int lane = tid & 31;
    const int wid  = tid >> 5;
    const int wm   = wid & 1;           // 0..1
    const int wn   = wid >> 1;          // 0..3
    const int bm   = blockIdx.y * 128;
    const int bn   = blockIdx.x * 128;

    // cp.async store slot for this thread (covers 4 rows, stride 32)
    const int srow = tid >> 3;          // 0..31
    const int scol = tid & 7;           // 16B unit
    const uint32_t stoff = (uint32_t)srow * 128 +
                           (uint32_t)((scol ^ (srow & 7)) << 4);
    const __nv_bfloat16* gA0 = A + (size_t)(bm + srow) * ldA + scol * 8;
    const __nv_bfloat16* gB0 = B + (size_t)(bn + srow) * ldB + scol * 8;

    float acc[4][4][4];
    #pragma unroll
    for (int i = 0; i < 4; i++)
        #pragma unroll
        for (int j = 0; j < 4; j++)
            #pragma unroll
            for (int r = 0; r < 4; r++) acc[i][j][r] = 0.f;

    // ldmatrix lane geometry
    const int g  = lane >> 3;           // group 0..3
    const int lr = lane & 7;
    const int rA = wm * 64 + lr + (g & 1) * 8;     // A row within tile
    const int chA = g >> 1;                         // k half (0: k0-7, 1: k8-15)
    const int sA7 = rA & 7;
    const int rB = wn * 32 + lr + (g >> 1) * 8;    // B row (n) within tile
    const int chB = g & 1;
    const int sB7 = rB & 7;

#define LOAD_STAGE(s, k0)                                                      \
    do {                                                                       \
        uint32_t dA = sbase + (s) * STAGE_BYTES + stoff;                       \
        const __nv_bfloat16* ga = gA0 + (k0);                                  \
        _Pragma("unroll")                                                      \
        for (int i = 0; i < 4; i++)                                            \
            cp16(dA + i * 4096, ga + (size_t)i * 32 * ldA);                    \
        uint32_t dB = sbase + (s) * STAGE_BYTES + 16384 + stoff;               \
        const __nv_bfloat16* gb = gB0 + (k0);                                  \
        _Pragma("unroll")                                                      \
        for (int i = 0; i < 4; i++)                                            \
            cp16(dB + i * 4096, gb + (size_t)i * 32 * ldB);                    \
        asm volatile("cp.async.commit_group;" ::: "memory");                   \
    } while (0)

    LOAD_STAGE(0, 0);
    LOAD_STAGE(1, 64);

    for (int c = 0; c < nchunks; c++) {
        if (c + 2 < nchunks) {
            asm volatile("cp.async.wait_group 1;" ::: "memory");
        } else {
            asm volatile("cp.async.wait_group 0;" ::: "memory");
        }
        __syncthreads();
        if (c + 2 < nchunks) {
            int s2 = (c + 2) % 3;
            LOAD_STAGE(s2, (c + 2) * 64);
        }

        const uint32_t aB = sbase + (c % 3) * STAGE_BYTES;
        const uint32_t bB = aB + 16384;
        #pragma unroll
        for (int ks = 0; ks < 4; ks++) {
            uint32_t a[4][4];
            #pragma unroll
            for (int mi = 0; mi < 4; mi++) {
                uint32_t addr = aB + (uint32_t)(rA + mi * 16) * 128 +
                                (uint32_t)((((2 * ks + chA) ^ sA7)) << 4);
                ldsm4(a[mi], addr);
            }
            uint32_t b[2][4];
            #pragma unroll
            for (int ng = 0; ng < 2; ng++) {
                uint32_t addr = bB + (uint32_t)(rB + ng * 16) * 128 +
                                (uint32_t)((((2 * ks + chB) ^ sB7)) << 4);
                ldsm4(b[ng], addr);
            }
            #pragma unroll
            for (int mi = 0; mi < 4; mi++)
                #pragma unroll
                for (int ni = 0; ni < 4; ni++)
                    mma_bf16(acc[mi][ni], a[mi],
                             b[ni >> 1][(ni & 1) * 2],
                             b[ni >> 1][(ni & 1) * 2 + 1]);
        }
        __syncthreads();
    }
#undef LOAD_STAGE

    // epilogue: write fp32 accumulators
    const int erow = lane >> 2;
    const int ecol = (lane & 3) * 2;
    #pragma unroll
    for (int mi = 0; mi < 4; mi++) {
        int row = bm + wm * 64 + mi * 16 + erow;
        #pragma unroll
        for (int ni = 0; ni < 4; ni++) {
            int col = bn + wn * 32 + ni * 8 + ecol;
            float2 v0 = make_float2(acc[mi][ni][0], acc[mi][ni][1]);
            float2 v1 = make_float2(acc[mi][ni][2], acc[mi][ni][3]);
            *reinterpret_cast<float2*>(C + (size_t)row * ldC + col) = v0;
            *reinterpret_cast<float2*>(C + (size_t)(row + 8) * ldC + col) = v1;
        }
    }
}

// ---------------- conversions: fp32 -> split bf16 (hi, lo) ----------------
__device__ __forceinline__ void split_bf16(float v, __nv_bfloat16& h, __nv_bfloat16& l) {
    h = __float2bfloat16(v);
    l = __float2bfloat16(v - __bfloat162float(h));
}
__device__ __forceinline__ void store4bf(__nv_bfloat16* p,
                                         __nv_bfloat16 a, __nv_bfloat16 b,
                                         __nv_bfloat16 c, __nv_bfloat16 d) {
    __nv_bfloat162 v0, v1;
    v0.x = a; v0.y = b; v1.x = c; v1.y = d;
    uint2 u;
    u.x = *reinterpret_cast<uint32_t*>(&v0);
    u.y = *reinterpret_cast<uint32_t*>(&v1);
    *reinterpret_cast<uint2*>(p) = u;
}

// A' for big GEMM: rows scaled by router weight w_s; segs [ah | ah | al]
__global__ void convert_A_kernel(const float* __restrict__ x0,
                                 const float* __restrict__ x1,
                                 const float* __restrict__ xib) {
    const int K4 = KCAT / 4;   // 704
    const int total = BATCH * K4;
    for (int idx = blockIdx.x * blockDim.x + threadIdx.x; idx < total;
         idx += gridDim.x * blockDim.x) {
        int b = idx / K4;
        int c = (idx - b * K4) * 4;
        float w; float4 v;
        if (c < D0) {
            w = g_w[b * 3 + 0];
            v = *reinterpret_cast<const float4*>(x0 + (size_t)b * D0 + c);
        } else if (c < D0 + D1) {
            w = g_w[b * 3 + 1];
            v = *reinterpret_cast<const float4*>(x1 + (size_t)b * D1 + (c - D0));
        } else {
            w = g_w[b * 3 + 2];
            v = *reinterpret_cast<const float4*>(xib + (size_t)b * DIB + (c - D0 - D1));
        }
        v.x *= w; v.y *= w; v.z *= w; v.w *= w;
        __nv_bfloat16 h[4], l[4];
        split_bf16(v.x, h[0], l[0]); split_bf16(v.y, h[1], l[1]);
        split_bf16(v.z, h[2], l[2]); split_bf16(v.w, h[3], l[3]);
        __nv_bfloat16* p = g_A + (size_t)b * KP_BIG + c;
        store4bf(p,            h[0], h[1], h[2], h[3]);
        store4bf(p + KCAT,     h[0], h[1], h[2], h[3]);
        store4bf(p + 2 * KCAT, l[0], l[1], l[2], l[3]);
    }
}

// A1' for router GEMM1 (x0, unscaled): segs [ah | ah | al]
__global__ void convert_A1_kernel(const float* __restrict__ x0) {
    const int K4 = D0 / 4;   // 256
    const int total = BATCH * K4;
    for (int idx = blockIdx.x * blockDim.x + threadIdx.x; idx < total;
         idx += gridDim.x * blockDim.x) {
        int b = idx >> 8;
        int c = (idx & 255) * 4;
        float4 v = *reinterpret_cast<const float4*>(x0 + (size_t)b * D0 + c);
        __nv_bfloat16 h[4], l[4];
        split_bf16(v.x, h[0], l[0]); split_bf16(v.y, h[1], l[1]);
        split_bf16(v.z, h[2], l[2]); split_bf16(v.w, h[3], l[3]);
        __nv_bfloat16* p = g_A1 + (size_t)b * KP_R1 + c;
        store4bf(p,          h[0], h[1], h[2], h[3]);
        store4bf(p + D0,     h[0], h[1], h[2], h[3]);
        store4bf(p + 2 * D0, l[0], l[1], l[2], l[3]);
    }
}

// B' for big GEMM: average 7 experts, transpose to [n][k'], segs [bh | bl | bh]
__global__ void convert_B_kernel(const float* __restrict__ pW0,
                                 const float* __restrict__ pW1,
                                 const float* __restrict__ pWib) {
    __shared__ float t[32][33];
    const int k0 = blockIdx.x * 32;
    const int n0 = blockIdx.y * 32;
    const int tx = threadIdx.x, ty = threadIdx.y;
    for (int kl = ty; kl < 32; kl += 8) {
        int k = k0 + kl;
        const float* src; int lr, ld;
        if (k < D0)            { src = pW0;  lr = k;            ld = D0;  }
        else if (k < D0 + D1)  { src = pW1;  lr = k - D0;       ld = D1;  }
        else                   { src = pWib; lr = k - D0 - D1;  ld = DIB; }
        const float* p = src + (size_t)lr * DOUT + n0 + tx;
        const size_t es = (size_t)ld * DOUT;
        float s = 0.f;
        #pragma unroll
        for (int e = 0; e < NEXP; e++) s += p[(size_t)e * es];
        t[kl][tx] = s * (1.0f / 7.0f);
    }
    __syncthreads();
    for (int nl = ty; nl < 32; nl += 8) {
        float v = t[tx][nl];
        __nv_bfloat16 h, l;
        split_bf16(v, h, l);
        size_t o = (size_t)(n0 + nl) * KP_BIG + k0 + tx;
        g_B[o]            = h;
        g_B[o + KCAT]     = l;
        g_B[o + 2 * KCAT] = h;
    }
}

// B1' for router GEMM1: transpose rw1[1024,512] to [n][k'], segs [bh | bl | bh]
__global__ void convert_B1_kernel(const float* __restrict__ rw1) {
    __shared__ float t[32][33];
    const int k0 = blockIdx.x * 32;
    const int n0 = blockIdx.y * 32;
    const int tx = threadIdx.x, ty = threadIdx.y;
    for (int kl = ty; kl < 32; kl += 8)
        t[kl][tx] = rw1[(size_t)(k0 + kl) * H1C + n0 + tx];
    __syncthreads();
    for (int nl = ty; nl < 32; nl += 8) {
        float v = t[tx][nl];
        __nv_bfloat16 h, l;
        split_bf16(v, h, l);
        size_t o = (size_t)(n0 + nl) * KP_R1 + k0 + tx;
        g_B1[o]          = h;
        g_B1[o + D0]     = l;
        g_B1[o + 2 * D0] = h;
    }
}

// ---------------- misc small kernels ----------------
__global__ void zero_stats_kernel() {
    int i = blockIdx.x * blockDim.x + threadIdx.x;
    if (i < 2 * H1C) g_stats1[i] = 0.0f;
    if (i < 2 * H2C) g_stats2[i] = 0.0f;
}

__global__ void avg_bias_kernel(const float* __restrict__ pb0,
                                const float* __restrict__ pb1,
                                const float* __restrict__ pbib) {
    int i = blockIdx.x * blockDim.x + threadIdx.x;
    if (i >= 3 * DOUT) return;
    int s = i / DOUT, n = i - s * DOUT;
    const float* pb = (s == 0) ? pb0 : (s == 1) ? pb1 : pbib;
    float a = 0.f;
    #pragma unroll
    for (int e = 0; e < NEXP; e++) a += pb[e * DOUT + n];
    g_bavg[i] = a * (1.0f / 7.0f);
}

// fp32 SGEMM kept for router layer 2 (N=100)
template<bool NGUARD>
__global__ void __launch_bounds__(256, 2)
sgemm_kernel(const float* __restrict__ A, const float* __restrict__ Bm,
             const float* __restrict__ bias, float* __restrict__ C,
             int M, int N, int K) {
    __shared__ float As[8][128];
    __shared__ float Bs[8][128];
    const int bm = blockIdx.y * 128;
    const int bn = blockIdx.x * 128;
    const int tid  = threadIdx.x;
    const int arow = tid >> 1;
    const int acol = (tid & 1) << 2;
    const int brow = tid >> 5;
    const int bcol = (tid & 31) << 2;
    const int tx = tid & 15;
    const int ty = tid >> 4;

    float acc[8][8];
    #pragma unroll
    for (int i = 0; i < 8; i++)
        #pragma unroll
        for (int j = 0; j < 8; j++) acc[i][j] = 0.f;

    for (int k0 = 0; k0 < K; k0 += 8) {
        float4 av = *reinterpret_cast<const float4*>(
            A + (size_t)(bm + arow) * K + k0 + acol);
        As[acol + 0][arow] = av.x;
        As[acol + 1][arow] = av.y;
        As[acol + 2][arow] = av.z;
        As[acol + 3][arow] = av.w;
        if (!NGUARD) {
            float4 bv = *reinterpret_cast<const float4*>(
                Bm + (size_t)(k0 + brow) * N + bn + bcol);
            *reinterpret_cast<float4*>(&Bs[brow][bcol]) = bv;
        } else {
            #pragma unroll
            for (int j = 0; j < 4; j++) {
                int n = bn + bcol + j;
                Bs[brow][bcol + j] = (n < N) ? Bm[(size_t)(k0 + brow) * N + n] : 0.f;
            }
        }
        __syncthreads();
        #pragma unroll
        for (int kk = 0; kk < 8; kk++) {
            float4 a0 = *reinterpret_cast<const float4*>(&As[kk][ty * 4]);
            float4 a1 = *reinterpret_cast<const float4*>(&As[kk][64 + ty * 4]);
            float4 b0 = *reinterpret_cast<const float4*>(&Bs[kk][tx * 4]);
            float4 b1 = *reinterpret_cast<const float4*>(&Bs[kk][64 + tx * 4]);
            float a[8] = {a0.x, a0.y, a0.z, a0.w, a1.x, a1.y, a1.z, a1.w};
            float b[8] = {b0.x, b0.y, b0.z, b0.w, b1.x, b1.y, b1.z, b1.w};
            #pragma unroll
            for (int i = 0; i < 8; i++)
                #pragma unroll
                for (int j = 0; j < 8; j++)
                    acc[i][j] = fmaf(a[i], b[j], acc[i][j]);
        }
        __syncthreads();
    }

    #pragma unroll
    for (int i = 0; i < 8; i++) {
        int m = bm + ((i < 4) ? (ty * 4 + i) : (64 + ty * 4 + (i - 4)));
        #pragma unroll
        for (int j = 0; j < 8; j++) {
            int n = bn + ((j < 4) ? (tx * 4 + j) : (64 + tx * 4 + (j - 4)));
            if (!NGUARD || n < N) {
                float v = acc[i][j];
                if (bias) v += bias[n];
                C[(size_t)m * N + n] = v;
            }
        }
    }
}

__global__ void col_stats_kernel(const float* __restrict__ H,
                                 float* __restrict__ stats, int Brows, int C) {
    int c = blockIdx.x * 32 + threadIdx.x;
    int chunk = (Brows + gridDim.y - 1) / gridDim.y;
    int r0 = blockIdx.y * chunk;
    int r1 = min(Brows, r0 + chunk);
    float s = 0.f, s2 = 0.f;
    if (c < C) {
        for (int r = r0 + threadIdx.y; r < r1; r += 8) {
            float v = H[(size_t)r * C + c];
            s += v;
            s2 = fmaf(v, v, s2);
        }
    }
    __shared__ float sh[8][2][32];
    sh[threadIdx.y][0][threadIdx.x] = s;
    sh[threadIdx.y][1][threadIdx.x] = s2;
    __syncthreads();
    if (threadIdx.y == 0 && c < C) {
        float ts = 0.f, ts2 = 0.f;
        #pragma unroll
        for (int y = 0; y < 8; y++) { ts += sh[y][0][threadIdx.x]; ts2 += sh[y][1][threadIdx.x]; }
        atomicAdd(&stats[c], ts);
        atomicAdd(&stats[C + c], ts2);
    }
}

__global__ void bn_relu_h1_kernel(const float* __restrict__ gamma,
                                  const float* __restrict__ beta) {
    const int total = BATCH * H1C;
    const float invB = 1.0f / (float)BATCH;
    for (int i = blockIdx.x * blockDim.x + threadIdx.x; i < total;
         i += gridDim.x * blockDim.x) {
        int c = i & (H1C - 1);
        float mean = g_stats1[c] * invB;
        float var  = g_stats1[H1C + c] * invB - mean * mean;
        float inv  = rsqrtf(var + 1e-5f);
        float v = g_h1[i];
        v = gamma[c] * (v - mean) * inv + beta[c];
        g_h1[i] = fmaxf(v, 0.f);
    }
}

__global__ void router_final_kernel(const float* __restrict__ rg2,
                                    const float* __restrict__ rbt2,
                                    const float* __restrict__ rw3,
                                    const float* __restrict__ rb3) {
    int warp = (blockIdx.x * blockDim.x + threadIdx.x) >> 5;
    int lane = threadIdx.x & 31;
    if (warp >= BATCH) return;
    const float invB = 1.0f / (float)BATCH;
    float d0 = 0.f, d1 = 0.f, d2 = 0.f;
    for (int c = lane; c < H2C; c += 32) {
        float mean = g_stats2[c] * invB;
        float var  = g_stats2[H2C + c] * invB - mean * mean;
        float v = g_h2[(size_t)warp * H2C + c];
        v = rg2[c] * (v - mean) * rsqrtf(var + 1e-5f) + rbt2[c];
        v = tanhf(v);
        d0 = fmaf(v, rw3[c * 3 + 0], d0);
        d1 = fmaf(v, rw3[c * 3 + 1], d1);
        d2 = fmaf(v, rw3[c * 3 + 2], d2);
    }
    #pragma unroll
    for (int o = 16; o > 0; o >>= 1) {
        d0 += __shfl_down_sync(0xffffffffu, d0, o);
        d1 += __shfl_down_sync(0xffffffffu, d1, o);
        d2 += __shfl_down_sync(0xffffffffu, d2, o);
    }
    if (lane == 0) {
        float l0 = 1.f / (1.f + __expf(-(d0 + rb3[0])));
        float l1 = 1.f / (1.f + __expf(-(d1 + rb3[1])));
        float l2 = 1.f / (1.f + __expf(-(d2 + rb3[2])));
        float mx = fmaxf(l0, fmaxf(l1, l2));
        float e0 = __expf(l0 - mx), e1 = __expf(l1 - mx), e2 = __expf(l2 - mx);
        float inv = 1.f / (e0 + e1 + e2);
        g_w[warp * 3 + 0] = e0 * inv;
        g_w[warp * 3 + 1] = e1 * inv;
        g_w[warp * 3 + 2] = e2 * inv;
    }
}

__global__ void normalize_rows_kernel(float* __restrict__ out) {
    int b = blockIdx.x;
    int t = threadIdx.x;
    float w0 = g_w[b * 3 + 0], w1 = g_w[b * 3 + 1], w2 = g_w[b * 3 + 2];
    float vals[6];
    float ss = 0.f;
    #pragma unroll
    for (int j = 0; j < 6; j++) {
        int n = t + j * 256;
        float v = out[(size_t)b * DOUT + n];
        v += w0 * g_bavg[n] + w1 * g_bavg[DOUT + n] + w2 * g_bavg[2 * DOUT + n];
        vals[j] = v;
        ss = fmaf(v, v, ss);
    }
    __shared__ float red[256];
    red[t] = ss;
    __syncthreads();
    #pragma unroll
    for (int s2 = 128; s2 > 0; s2 >>= 1) {
        if (t < s2) red[t] += red[t + s2];
        __syncthreads();
    }
    float inv = 1.f / fmaxf(sqrtf(red[0]), 1e-12f);
    #pragma unroll
    for (int j = 0; j < 6; j++)
        out[(size_t)b * DOUT + t + j * 256] = vals[j] * inv;
}

// ---------------- launch ----------------
extern "C" void kernel_launch(void* const* d_in, const int* in_sizes, int n_in,
                              void* d_out, int out_size) {
    const float* x0   = (const float*)d_in[0];
    const float* x1   = (const float*)d_in[1];
    const float* xib  = (const float*)d_in[2];
    const float* pW0  = (const float*)d_in[3];
    const float* pb0  = (const float*)d_in[4];
    const float* pW1  = (const float*)d_in[5];
    const float* pb1  = (const float*)d_in[6];
    const float* pWib = (const float*)d_in[7];
    const float* pbib = (const float*)d_in[8];
    const float* rw1  = (const float*)d_in[9];
    // rb1 (d_in[10]) cancels exactly under batch-norm — skipped
    const float* rg1  = (const float*)d_in[11];
    const float* rbt1 = (const float*)d_in[12];
    const float* rw2  = (const float*)d_in[13];
    const float* rb2  = (const float*)d_in[14];
    const float* rg2  = (const float*)d_in[15];
    const float* rbt2 = (const float*)d_in[16];
    const float* rw3  = (const float*)d_in[17];
    const float* rb3  = (const float*)d_in[18];
    float* out = (float*)d_out;
    (void)in_sizes; (void)n_in; (void)out_size;

    void *a_p, *b_p, *a1_p, *b1_p, *h1_p, *h2_p, *s1_p, *s2_p;
    cudaGetSymbolAddress(&a_p,  g_A);
    cudaGetSymbolAddress(&b_p,  g_B);
    cudaGetSymbolAddress(&a1_p, g_A1);
    cudaGetSymbolAddress(&b1_p, g_B1);
    cudaGetSymbolAddress(&h1_p, g_h1);
    cudaGetSymbolAddress(&h2_p, g_h2);
    cudaGetSymbolAddress(&s1_p, g_stats1);
    cudaGetSymbolAddress(&s2_p, g_stats2);
    const __nv_bfloat16* Ab  = (const __nv_bfloat16*)a_p;
    const __nv_bfloat16* Bb  = (const __nv_bfloat16*)b_p;
    const __nv_bfloat16* A1b = (const __nv_bfloat16*)a1_p;
    const __nv_bfloat16* B1b = (const __nv_bfloat16*)b1_p;
    float* h1  = (float*)h1_p;
    float* h2  = (float*)h2_p;
    float* st1 = (float*)s1_p;
    float* st2 = (float*)s2_p;

    cudaFuncSetAttribute(hmma_gemm_kernel,
                         cudaFuncAttributeMaxDynamicSharedMemorySize, HM_SMEM);

    zero_stats_kernel<<<4, 256>>>();
    avg_bias_kernel<<<(3 * DOUT + 255) / 256, 256>>>(pb0, pb1, pbib);

    // weight-side conversions (independent of router)
    convert_B_kernel <<<dim3(KCAT / 32, DOUT / 32), dim3(32, 8)>>>(pW0, pW1, pWib);
    convert_B1_kernel<<<dim3(D0 / 32, H1C / 32),   dim3(32, 8)>>>(rw1);
    convert_A1_kernel<<<4096, 256>>>(x0);

    // router layer 1 on HMMA: h1 = x0 @ rw1  (bias dropped; cancels in BN)
    hmma_gemm_kernel<<<dim3(H1C / 128, BATCH / 128), 256, HM_SMEM>>>(
        A1b, B1b, h1, KP_R1, KP_R1, H1C, KP_R1 / 64);
    col_stats_kernel<<<dim3(H1C / 32, 16), dim3(32, 8)>>>(h1, st1, BATCH, H1C);
    bn_relu_h1_kernel<<<4096, 256>>>(rg1, rbt1);

    // router layer 2 (small, fp32): h2 = h1 @ rw2 + rb2
    sgemm_kernel<true><<<dim3(1, BATCH / 128), 256>>>(
        h1, rw2, rb2, h2, BATCH, H2C, H1C);
    col_stats_kernel<<<dim3((H2C + 31) / 32, 16), dim3(32, 8)>>>(h2, st2, BATCH, H2C);
    router_final_kernel<<<BATCH * 32 / 256, 256>>>(rg2, rbt2, rw3, rb3);

    // big GEMM on HMMA: out = (w-scaled Xcat) @ Wavg, split-bf16
    convert_A_kernel<<<8192, 256>>>(x0, x1, xib);
    hmma_gemm_kernel<<<dim3(DOUT / 128, BATCH / 128), 256, HM_SMEM>>>(
        Ab, Bb, out, KP_BIG, KP_BIG, DOUT, KP_BIG / 64);

    normalize_rows_kernel<<<BATCH, 256>>>(out);
}